// round 2
// baseline (speedup 1.0000x reference)
#include <cuda_runtime.h>
#include <math.h>
#include <float.h>

// Problem dims
#define NB 128
#define ND 256
#define NS 512
#define NK 50
#define NH 256
#define NROWS (NB*NS)            // 65536 (b,s) rows
#define OUT_PRED 0               // 256 floats
#define OUT_SCAL0 256            // 0.0f
#define OUT_SIM 257
#define OUT_FAR 258
#define OUT_NN 259               // B*S*K floats
#define OUT_AE (259 + NROWS*NK)  // 3277059

// ---------------- device scratch (no allocs allowed) ----------------
__device__ float g_tvn[ND*NK];            // normalized topic vectors [D][K]
__device__ float g_invnorm[NROWS];        // 1/max(||x_bs||,1e-12)
__device__ float g_tpnT[NK*NROWS];        // topic_prob_n transposed [K][B*S] (13MB)
__device__ float g_rec1[NROWS*NH];        // relu(nn@rv1) (64MB)
__device__ float g_cand[NK*64*32];        // stage-1 top-k candidates
__device__ float g_mean[NB*ND];           // sum_s rec2[b,s,d]
__device__ float g_ae;
__device__ float g_sim;
__device__ float g_far;

// ---------------- kernel 0: tv normalize + concept_far + zero accum ----------------
__global__ void prep_kernel(const float* __restrict__ tv) {
    __shared__ float inv[64];
    __shared__ float red[256];
    int tid = threadIdx.x;
    if (tid < NK) {
        float ss = 0.f;
        for (int d = 0; d < ND; d++) { float v = tv[d*NK + tid]; ss += v*v; }
        inv[tid] = 1.0f / fmaxf(sqrtf(ss), 1e-12f);
    }
    __syncthreads();
    for (int i = tid; i < ND*NK; i += 256) g_tvn[i] = tv[i] * inv[i % NK];
    for (int i = tid; i < NB*ND; i += 256) g_mean[i] = 0.f;
    if (tid == 0) { g_ae = 0.f; g_sim = 0.f; }
    __syncthreads();
    // concept_far = mean(tvn^T tvn - I)
    float acc = 0.f;
    for (int p = tid; p < NK*NK; p += 256) {
        int i = p / NK, j = p % NK;
        float ds = 0.f;
        for (int d = 0; d < ND; d++) ds += g_tvn[d*NK + i] * g_tvn[d*NK + j];
        acc += ds - ((i == j) ? 1.0f : 0.0f);
    }
    red[tid] = acc; __syncthreads();
    for (int s = 128; s > 0; s >>= 1) { if (tid < s) red[tid] += red[tid+s]; __syncthreads(); }
    if (tid == 0) g_far = red[0] / (float)(NK*NK);
}

// ---------------- kernel 1: topic probs, norms, mask, nn ----------------
// grid (S/32, B), 256 threads. dyn smem layout (floats):
// tvs[12800] | xt[32*257] | tpn[32*51] | am[32*51] | inv_s[32] | den_s[32]
#define K1_SMEM_FLOATS (12800 + 32*257 + 32*51 + 32*51 + 32 + 32)
__global__ void topic_kernel(const float* __restrict__ f, float* __restrict__ out_nn) {
    extern __shared__ float sm[];
    float* tvs   = sm;
    float* xt    = tvs + 12800;
    float* tpn   = xt + 32*257;
    float* am    = tpn + 32*51;
    float* inv_s = am + 32*51;
    float* den_s = inv_s + 32;

    int tid = threadIdx.x;
    int b = blockIdx.y;
    int s0 = blockIdx.x * 32;
    int row0 = b * NS + s0;

    for (int i = tid; i < ND*NK; i += 256) tvs[i] = g_tvn[i];
    const float* fb = f + (size_t)b * ND * NS + s0;
    for (int i = tid; i < ND*32; i += 256) {
        int d = i >> 5, sl = i & 31;
        xt[sl*257 + d] = fb[(size_t)d*NS + sl];
    }
    __syncthreads();

    // per-s norms: warp w handles 4 s values
    int w = tid >> 5, lane = tid & 31;
    for (int s = w*4; s < w*4+4; s++) {
        float ss = 0.f;
        for (int d = lane; d < ND; d += 32) { float v = xt[s*257 + d]; ss += v*v; }
        for (int o = 16; o; o >>= 1) ss += __shfl_down_sync(0xffffffffu, ss, o);
        if (lane == 0) {
            float iv = 1.0f / fmaxf(sqrtf(ss), 1e-12f);
            inv_s[s] = iv;
            g_invnorm[row0 + s] = iv;
        }
    }
    __syncthreads();

    // dot products: 32 s * 25 k-pairs = 800 tasks
    for (int t = tid; t < 800; t += 256) {
        int s = t / 25;
        int k = (t % 25) * 2;
        const float* xr = xt + s*257;
        float a0 = 0.f, a1 = 0.f;
        #pragma unroll 8
        for (int d = 0; d < ND; d++) {
            float xv = xr[d];
            float2 tv2 = *(const float2*)&tvs[d*NK + k];
            a0 += xv * tv2.x;
            a1 += xv * tv2.y;
        }
        float iv = inv_s[s];
        float t0 = a0 * iv, t1 = a1 * iv;
        tpn[s*51 + k]     = t0;
        tpn[s*51 + k + 1] = t1;
        am[s*51 + k]      = (t0 > 0.3f) ? a0 : 0.f;
        am[s*51 + k + 1]  = (t1 > 0.3f) ? a1 : 0.f;
    }
    __syncthreads();

    if (tid < 32) {
        float ssum = 0.f;
        for (int k = 0; k < NK; k++) ssum += am[tid*51 + k];
        den_s[tid] = 1.0f / (ssum + 0.001f + 1e-8f);
    }
    __syncthreads();

    for (int t = tid; t < 32*NK; t += 256) {
        int s = t / NK, k = t - s*NK;
        out_nn[(size_t)(row0 + s)*NK + k] = am[s*51 + k] * den_s[s];
    }
    for (int t = tid; t < 32*NK; t += 256) {
        int k = t >> 5, sl = t & 31;
        g_tpnT[(size_t)k*NROWS + row0 + sl] = tpn[sl*51 + k];
    }
}

// ---------------- top-k stage 1: per-(concept,1024-chunk) top-32 ----------------
// grid (64 chunks, 50 concepts), 32 threads (one warp)
__global__ void topk1_kernel() {
    int k = blockIdx.y, chunk = blockIdx.x, lane = threadIdx.x;
    const float* src = g_tpnT + (size_t)k*NROWS + chunk*1024;
    float v[32];
    #pragma unroll
    for (int j = 0; j < 32; j++) v[j] = src[j*32 + lane];
    float* dst = g_cand + ((size_t)k*64 + chunk)*32;
    for (int it = 0; it < 32; it++) {
        float lm = -FLT_MAX;
        #pragma unroll
        for (int j = 0; j < 32; j++) lm = fmaxf(lm, v[j]);
        float wm = lm;
        for (int o = 16; o; o >>= 1) wm = fmaxf(wm, __shfl_xor_sync(0xffffffffu, wm, o));
        unsigned msk = __ballot_sync(0xffffffffu, lm == wm);
        int owner = __ffs(msk) - 1;
        if (lane == owner) {
            dst[it] = wm;
            bool rm = false;
            #pragma unroll
            for (int j = 0; j < 32; j++)
                if (!rm && v[j] == wm) { v[j] = -FLT_MAX; rm = true; }
        }
        __syncwarp();
    }
}

// ---------------- top-k stage 2: per-concept global top-32 from 2048 cands ----------------
__global__ void topk2_kernel() {
    __shared__ float cd[2048];
    __shared__ float sval[256];
    __shared__ int   sidx[256];
    int tid = threadIdx.x, k = blockIdx.x;
    for (int i = tid; i < 2048; i += 256) cd[i] = g_cand[(size_t)k*2048 + i];
    __syncthreads();
    float total = 0.f;
    for (int it = 0; it < 32; it++) {
        float lm = -FLT_MAX; int li = tid;
        for (int j = tid; j < 2048; j += 256)
            if (cd[j] > lm) { lm = cd[j]; li = j; }
        sval[tid] = lm; sidx[tid] = li;
        __syncthreads();
        for (int s = 128; s > 0; s >>= 1) {
            if (tid < s && sval[tid+s] > sval[tid]) { sval[tid] = sval[tid+s]; sidx[tid] = sidx[tid+s]; }
            __syncthreads();
        }
        if (tid == 0) { total += sval[0]; cd[sidx[0]] = -FLT_MAX; }
        __syncthreads();
    }
    if (tid == 0) atomicAdd(&g_sim, total);
}

// ---------------- kernel 2: rec1 = relu(nn @ rv1) ----------------
// grid NROWS/64, 256 threads. dyn smem: rv1s[50*256] | nns[64*52]
#define K2_SMEM_FLOATS (NK*NH + 64*52)
__global__ void rec1_kernel(const float* __restrict__ rv1, const float* __restrict__ nn_in) {
    extern __shared__ float sm[];
    float* rv1s = sm;
    float* nns  = sm + NK*NH;
    int tid = threadIdx.x;
    int row0 = blockIdx.x * 64;
    for (int i = tid; i < NK*NH; i += 256) rv1s[i] = rv1[i];
    for (int i = tid; i < 64*NK; i += 256) {
        int r = i / NK, k = i - r*NK;
        nns[r*52 + k] = nn_in[(size_t)row0*NK + i];
    }
    if (tid < 64) { nns[tid*52 + 50] = 0.f; nns[tid*52 + 51] = 0.f; }
    __syncthreads();
    float w[52];
    #pragma unroll
    for (int k = 0; k < NK; k++) w[k] = rv1s[k*NH + tid];
    w[50] = 0.f; w[51] = 0.f;
    for (int r = 0; r < 64; r++) {
        const float4* nr = (const float4*)(nns + r*52);
        float acc = 0.f;
        #pragma unroll
        for (int q = 0; q < 13; q++) {
            float4 v = nr[q];
            acc += v.x*w[4*q] + v.y*w[4*q+1] + v.z*w[4*q+2] + v.w*w[4*q+3];
        }
        g_rec1[(size_t)(row0 + r)*NH + tid] = fmaxf(acc, 0.f);
    }
}

// ---------------- kernel 3: rec2 = rec1 @ rv2, fused ae_loss + column sums ----------------
// 128x128x16 tiling, 256 threads (16x16), 8x8 microtile. grid (2, 512).
__global__ void rec2_kernel(const float* __restrict__ f, const float* __restrict__ rv2) {
    __shared__ float As[16*128];
    __shared__ float Bs[16*128];
    int tid = threadIdx.x;
    int tx = tid & 15, ty = tid >> 4;
    int col0 = blockIdx.x * 128;
    int row0 = blockIdx.y * 128;

    float acc[8][8];
    #pragma unroll
    for (int i = 0; i < 8; i++)
        #pragma unroll
        for (int j = 0; j < 8; j++) acc[i][j] = 0.f;

    for (int k0 = 0; k0 < NH; k0 += 16) {
        #pragma unroll
        for (int it = 0; it < 2; it++) {
            int v = tid + it*256;
            int r = v >> 2, q = v & 3;
            float4 t4 = *(const float4*)&g_rec1[(size_t)(row0 + r)*NH + k0 + q*4];
            As[(q*4+0)*128 + r] = t4.x;
            As[(q*4+1)*128 + r] = t4.y;
            As[(q*4+2)*128 + r] = t4.z;
            As[(q*4+3)*128 + r] = t4.w;
            int kk = v >> 5, qq = v & 31;
            float4 u4 = *(const float4*)&rv2[(size_t)(k0 + kk)*ND + col0 + qq*4];
            *(float4*)&Bs[kk*128 + qq*4] = u4;
        }
        __syncthreads();
        #pragma unroll
        for (int kk = 0; kk < 16; kk++) {
            float a[8], bb[8];
            *(float4*)&a[0]  = *(const float4*)&As[kk*128 + ty*8];
            *(float4*)&a[4]  = *(const float4*)&As[kk*128 + ty*8 + 4];
            *(float4*)&bb[0] = *(const float4*)&Bs[kk*128 + tx*8];
            *(float4*)&bb[4] = *(const float4*)&Bs[kk*128 + tx*8 + 4];
            #pragma unroll
            for (int i = 0; i < 8; i++)
                #pragma unroll
                for (int j = 0; j < 8; j++)
                    acc[i][j] += a[i]*bb[j];
        }
        __syncthreads();
    }

    // epilogue: ae_loss + per-col (= per-d) sums over rows (= over s)
    int b = row0 >> 9;           // 512 rows per b, tiles aligned
    int sbase = (row0 & 511) + ty*8;
    float invn[8];
    #pragma unroll
    for (int i = 0; i < 8; i++) invn[i] = g_invnorm[row0 + ty*8 + i];
    float aeacc = 0.f;
    float cs[8];
    #pragma unroll
    for (int j = 0; j < 8; j++) cs[j] = 0.f;
    #pragma unroll
    for (int j = 0; j < 8; j++) {
        int col = col0 + tx*8 + j;
        const float* fp = f + ((size_t)(b*ND + col))*NS + sbase;
        #pragma unroll
        for (int i = 0; i < 8; i++) {
            float c = acc[i][j];
            float xn = fp[i] * invn[i];
            float d = xn - c;
            aeacc += d*d;
            cs[j] += c;
        }
    }
    __syncthreads();
    #pragma unroll
    for (int j = 0; j < 8; j++) As[ty*128 + tx*8 + j] = cs[j];
    __syncthreads();
    if (tid < 128) {
        float ssum = 0.f;
        #pragma unroll
        for (int t = 0; t < 16; t++) ssum += As[t*128 + tid];
        atomicAdd(&g_mean[b*ND + col0 + tid], ssum);
    }
    Bs[tid] = aeacc;
    __syncthreads();
    for (int s = 128; s > 0; s >>= 1) { if (tid < s) Bs[tid] += Bs[tid+s]; __syncthreads(); }
    if (tid == 0) atomicAdd(&g_ae, Bs[0]);
}

// ---------------- final: pred head + scalars ----------------
__global__ void final_kernel(const float* __restrict__ Wc, const float* __restrict__ bc,
                             float* __restrict__ out) {
    int tid = threadIdx.x;
    int b = tid >> 1, c = tid & 1;
    float acc = 0.f;
    for (int d = 0; d < ND; d++) acc += g_mean[b*ND + d] * Wc[d*2 + c];
    out[OUT_PRED + b*2 + c] = acc * (1.0f/512.0f) + bc[c];
    if (tid == 0) {
        out[OUT_SCAL0] = 0.0f;
        out[OUT_SIM]   = -g_sim / (float)(NK * (NB/4));
        out[OUT_FAR]   = g_far;
        out[OUT_AE]    = g_ae / (float)((size_t)NROWS * ND);
    }
}

extern "C" void kernel_launch(void* const* d_in, const int* in_sizes, int n_in,
                              void* d_out, int out_size) {
    const float* f   = (const float*)d_in[0];   // f_input [B,D,S]
    // d_in[1] targets (unused)
    const float* tv  = (const float*)d_in[2];   // topic_vector [D,K]
    const float* rv1 = (const float*)d_in[3];   // [K,H]
    const float* rv2 = (const float*)d_in[4];   // [H,D]
    const float* Wc  = (const float*)d_in[5];   // [D,NCLS]
    const float* bc  = (const float*)d_in[6];   // [NCLS]
    float* out = (float*)d_out;

    cudaFuncSetAttribute(topic_kernel, cudaFuncAttributeMaxDynamicSharedMemorySize,
                         K1_SMEM_FLOATS * (int)sizeof(float));
    cudaFuncSetAttribute(rec1_kernel, cudaFuncAttributeMaxDynamicSharedMemorySize,
                         K2_SMEM_FLOATS * (int)sizeof(float));

    prep_kernel<<<1, 256>>>(tv);
    topic_kernel<<<dim3(NS/32, NB), 256, K1_SMEM_FLOATS * sizeof(float)>>>(f, out + OUT_NN);
    topk1_kernel<<<dim3(64, NK), 32>>>();
    rec1_kernel<<<NROWS/64, 256, K2_SMEM_FLOATS * sizeof(float)>>>(rv1, out + OUT_NN);
    topk2_kernel<<<NK, 256>>>();
    rec2_kernel<<<dim3(ND/128, NROWS/128), 256>>>(f, rv2);
    final_kernel<<<1, 256>>>(Wc, bc, out);
}

// round 3
// speedup vs baseline: 1.3425x; 1.3425x over previous
#include <cuda_runtime.h>
#include <math.h>
#include <float.h>

// Problem dims
#define NB 128
#define ND 256
#define NS 512
#define NK 50
#define NH 256
#define NROWS (NB*NS)            // 65536 (b,s) rows
#define OUT_PRED 0               // 256 floats
#define OUT_SCAL0 256            // 0.0f
#define OUT_SIM 257
#define OUT_FAR 258
#define OUT_NN 259               // B*S*K floats
#define OUT_AE (259 + NROWS*NK)  // 3277059

typedef unsigned long long ull;

// ---------------- packed f32x2 helpers (FFMA2) ----------------
__device__ __forceinline__ ull pack_dup(float a) {
    ull r; asm("mov.b64 %0, {%1, %1};" : "=l"(r) : "f"(a)); return r;
}
__device__ __forceinline__ void ffma2(ull &c, ull a, ull b) {
    asm("fma.rn.f32x2 %0, %1, %2, %0;" : "+l"(c) : "l"(a), "l"(b));
}
__device__ __forceinline__ float2 unpack2(ull v) {
    float2 f; asm("mov.b64 {%0, %1}, %2;" : "=f"(f.x), "=f"(f.y) : "l"(v)); return f;
}

// ---------------- device scratch (no allocs allowed) ----------------
__device__ __align__(16) float g_tvn[ND*NK];      // normalized topic vectors [D][K]
__device__ __align__(16) float g_tvnp[ND*64];     // padded [D][64] (k>=50 zero)
__device__ __align__(16) float g_invnorm[NROWS];  // 1/max(||x_bs||,1e-12)
__device__ __align__(16) float g_tpnT[NK*NROWS];  // topic_prob_n transposed [K][B*S]
__device__ __align__(16) float g_nn[NROWS*NK];    // aligned copy of topic_prob_nn
__device__ __align__(16) float g_rec1[NROWS*NH];  // relu(nn@rv1)
__device__ __align__(16) float g_cand[NK*64*32];  // stage-1 top-k candidates
__device__ __align__(16) float g_mean[NB*ND];     // sum_s rec2[b,s,d]
__device__ float g_ae;
__device__ float g_sim;
__device__ float g_far;

// ---------------- kernel 0: tv normalize + pad + concept_far + zero accum ----------------
__global__ void prep_kernel(const float* __restrict__ tv) {
    __shared__ float inv[64];
    __shared__ float red[256];
    int tid = threadIdx.x;
    if (tid < NK) {
        float ss = 0.f;
        for (int d = 0; d < ND; d++) { float v = tv[d*NK + tid]; ss += v*v; }
        inv[tid] = 1.0f / fmaxf(sqrtf(ss), 1e-12f);
    }
    __syncthreads();
    for (int i = tid; i < ND*NK; i += 256) g_tvn[i] = tv[i] * inv[i % NK];
    for (int i = tid; i < NB*ND; i += 256) g_mean[i] = 0.f;
    if (tid == 0) { g_ae = 0.f; g_sim = 0.f; }
    __syncthreads();
    // padded copy [D][64]
    for (int i = tid; i < ND*64; i += 256) {
        int d = i >> 6, k = i & 63;
        g_tvnp[i] = (k < NK) ? g_tvn[d*NK + k] : 0.f;
    }
    // concept_far = mean(tvn^T tvn - I)
    float acc = 0.f;
    for (int p = tid; p < NK*NK; p += 256) {
        int i = p / NK, j = p % NK;
        float ds = 0.f;
        for (int d = 0; d < ND; d++) ds += g_tvn[d*NK + i] * g_tvn[d*NK + j];
        acc += ds - ((i == j) ? 1.0f : 0.0f);
    }
    red[tid] = acc; __syncthreads();
    for (int s = 128; s > 0; s >>= 1) { if (tid < s) red[tid] += red[tid+s]; __syncthreads(); }
    if (tid == 0) g_far = red[0] / (float)(NK*NK);
}

// ---------------- kernel 1: topic GEMM 128x64xK256 + fused norm/mask/nn ----------------
// grid NROWS/128, 256 threads (tx 16 cols-groups x ty 16 rows-groups), 8 rows x 4 cols each
__global__ void __launch_bounds__(256) topic_kernel(const float* __restrict__ f,
                                                    float* __restrict__ out_nn) {
    __shared__ float As[16*128];     // [kk][row]
    __shared__ float Bs[16*64];      // [kk][k]
    __shared__ float spart[128*16];  // partial row sums
    __shared__ float inv_s[128];
    __shared__ float den_s[128];

    int tid = threadIdx.x;
    int tx = tid & 15, ty = tid >> 4;
    int row0 = blockIdx.x * 128;
    int b = row0 >> 9;
    int s00 = row0 & 511;

    ull acc2[8][2];
    #pragma unroll
    for (int i = 0; i < 8; i++) { acc2[i][0] = 0ull; acc2[i][1] = 0ull; }
    float ssq[8];
    #pragma unroll
    for (int i = 0; i < 8; i++) ssq[i] = 0.f;

    for (int d0 = 0; d0 < ND; d0 += 16) {
        // A tile: As[kk][r] = f[b, d0+kk, s00+r], coalesced
        #pragma unroll
        for (int it = 0; it < 2; it++) {
            int v = tid + it*256;
            int kk = v >> 5, r4 = (v & 31) * 4;
            float4 t4 = *(const float4*)(f + ((size_t)(b*ND + d0 + kk))*NS + s00 + r4);
            *(float4*)&As[kk*128 + r4] = t4;
        }
        // B tile: Bs[kk][k] = g_tvnp[(d0+kk)*64 + k]
        {
            int kk = tid >> 4, j4 = (tid & 15) * 4;
            *(float4*)&Bs[kk*64 + j4] = *(const float4*)&g_tvnp[(d0 + kk)*64 + j4];
        }
        __syncthreads();
        #pragma unroll
        for (int kk = 0; kk < 16; kk++) {
            float a[8];
            *(float4*)&a[0] = *(const float4*)&As[kk*128 + ty*8];
            *(float4*)&a[4] = *(const float4*)&As[kk*128 + ty*8 + 4];
            ulonglong2 bp = *(const ulonglong2*)&Bs[kk*64 + tx*4];
            ull b0 = bp.x, b1 = bp.y;
            #pragma unroll
            for (int i = 0; i < 8; i++) {
                ull ad = pack_dup(a[i]);
                ffma2(acc2[i][0], ad, b0);
                ffma2(acc2[i][1], ad, b1);
            }
            if (tx == 0) {
                #pragma unroll
                for (int i = 0; i < 8; i++) ssq[i] += a[i]*a[i];
            }
        }
        __syncthreads();
    }

    if (tx == 0) {
        #pragma unroll
        for (int i = 0; i < 8; i++) {
            float iv = 1.0f / fmaxf(sqrtf(ssq[i]), 1e-12f);
            inv_s[ty*8 + i] = iv;
            g_invnorm[row0 + ty*8 + i] = iv;
        }
    }
    __syncthreads();

    float tp[8][4], amv[8][4], iv[8];
    #pragma unroll
    for (int i = 0; i < 8; i++) iv[i] = inv_s[ty*8 + i];
    #pragma unroll
    for (int i = 0; i < 8; i++) {
        float2 c0 = unpack2(acc2[i][0]);
        float2 c1 = unpack2(acc2[i][1]);
        tp[i][0] = c0.x; tp[i][1] = c0.y; tp[i][2] = c1.x; tp[i][3] = c1.y;
        float psum = 0.f;
        #pragma unroll
        for (int j = 0; j < 4; j++) {
            float t = tp[i][j] * iv[i];
            float am = (t > 0.3f) ? tp[i][j] : 0.f;
            amv[i][j] = am;
            psum += am;                 // pad cols are exactly 0
        }
        spart[(ty*8 + i)*16 + tx] = psum;
    }
    __syncthreads();
    if (tid < 128) {
        float s = 0.f;
        #pragma unroll
        for (int t = 0; t < 16; t++) s += spart[tid*16 + t];
        den_s[tid] = 1.0f / ((s + 0.001f) + 1e-8f);
    }
    __syncthreads();

    #pragma unroll
    for (int i = 0; i < 8; i++) {
        int row = row0 + ty*8 + i;
        float den = den_s[ty*8 + i];
        #pragma unroll
        for (int j = 0; j < 4; j++) {
            int k = tx*4 + j;
            if (k < NK) {
                float v = amv[i][j] * den;
                out_nn[(size_t)row*NK + k] = v;
                g_nn[(size_t)row*NK + k] = v;
                g_tpnT[(size_t)k*NROWS + row] = tp[i][j] * iv[i];
            }
        }
    }
}

// ---------------- top-k stage 1: per-(concept,1024-chunk) top-32 ----------------
__global__ void topk1_kernel() {
    int k = blockIdx.y, chunk = blockIdx.x, lane = threadIdx.x;
    const float* src = g_tpnT + (size_t)k*NROWS + chunk*1024;
    float v[32];
    #pragma unroll
    for (int j = 0; j < 32; j++) v[j] = src[j*32 + lane];
    float* dst = g_cand + ((size_t)k*64 + chunk)*32;
    for (int it = 0; it < 32; it++) {
        float lm = -FLT_MAX;
        #pragma unroll
        for (int j = 0; j < 32; j++) lm = fmaxf(lm, v[j]);
        float wm = lm;
        for (int o = 16; o; o >>= 1) wm = fmaxf(wm, __shfl_xor_sync(0xffffffffu, wm, o));
        unsigned msk = __ballot_sync(0xffffffffu, lm == wm);
        int owner = __ffs(msk) - 1;
        if (lane == owner) {
            dst[it] = wm;
            bool rm = false;
            #pragma unroll
            for (int j = 0; j < 32; j++)
                if (!rm && v[j] == wm) { v[j] = -FLT_MAX; rm = true; }
        }
        __syncwarp();
    }
}

// ---------------- top-k stage 2 ----------------
__global__ void topk2_kernel() {
    __shared__ float cd[2048];
    __shared__ float sval[256];
    __shared__ int   sidx[256];
    int tid = threadIdx.x, k = blockIdx.x;
    for (int i = tid; i < 2048; i += 256) cd[i] = g_cand[(size_t)k*2048 + i];
    __syncthreads();
    float total = 0.f;
    for (int it = 0; it < 32; it++) {
        float lm = -FLT_MAX; int li = tid;
        for (int j = tid; j < 2048; j += 256)
            if (cd[j] > lm) { lm = cd[j]; li = j; }
        sval[tid] = lm; sidx[tid] = li;
        __syncthreads();
        for (int s = 128; s > 0; s >>= 1) {
            if (tid < s && sval[tid+s] > sval[tid]) { sval[tid] = sval[tid+s]; sidx[tid] = sidx[tid+s]; }
            __syncthreads();
        }
        if (tid == 0) { total += sval[0]; cd[sidx[0]] = -FLT_MAX; }
        __syncthreads();
    }
    if (tid == 0) atomicAdd(&g_sim, total);
}

// ---------------- kernel 2: rec1 GEMM 128x128xK50, relu ----------------
// grid (2, 512), 256 threads, 8x8 microtile, FFMA2
#define REC1_SMEM (2 * NK * 128 * 4)
__global__ void __launch_bounds__(256) rec1_kernel(const float* __restrict__ rv1) {
    extern __shared__ float sm[];
    float* As = sm;            // [k][row] 50*128
    float* Bs = sm + NK*128;   // [k][col] 50*128
    int tid = threadIdx.x;
    int tx = tid & 15, ty = tid >> 4;
    int col0 = blockIdx.x * 128;
    int row0 = blockIdx.y * 128;

    // A: g_nn rows row0..+128 (contiguous 6400 floats)
    const float* src = g_nn + (size_t)row0 * NK;
    for (int v = tid; v < 3200; v += 256) {
        float2 t = *(const float2*)(src + v*2);
        int idx = v*2;
        int r = idx / NK, k = idx - r*NK;  // k even, k+1 same row
        As[k*128 + r] = t.x;
        As[(k+1)*128 + r] = t.y;
    }
    // B: rv1[k][col0+j]
    for (int v = tid; v < 1600; v += 256) {
        int k = v >> 5, j4 = (v & 31) * 4;
        *(float4*)&Bs[k*128 + j4] = *(const float4*)(rv1 + k*NH + col0 + j4);
    }
    __syncthreads();

    ull acc2[8][4];
    #pragma unroll
    for (int i = 0; i < 8; i++)
        #pragma unroll
        for (int j = 0; j < 4; j++) acc2[i][j] = 0ull;

    #pragma unroll 2
    for (int k = 0; k < NK; k++) {
        float a[8];
        *(float4*)&a[0] = *(const float4*)&As[k*128 + ty*8];
        *(float4*)&a[4] = *(const float4*)&As[k*128 + ty*8 + 4];
        ulonglong2 b01 = *(const ulonglong2*)&Bs[k*128 + tx*8];
        ulonglong2 b23 = *(const ulonglong2*)&Bs[k*128 + tx*8 + 4];
        ull bb[4] = {b01.x, b01.y, b23.x, b23.y};
        #pragma unroll
        for (int i = 0; i < 8; i++) {
            ull ad = pack_dup(a[i]);
            #pragma unroll
            for (int j = 0; j < 4; j++) ffma2(acc2[i][j], ad, bb[j]);
        }
    }

    #pragma unroll
    for (int i = 0; i < 8; i++) {
        int row = row0 + ty*8 + i;
        float o[8];
        #pragma unroll
        for (int j = 0; j < 4; j++) {
            float2 c = unpack2(acc2[i][j]);
            o[j*2]   = fmaxf(c.x, 0.f);
            o[j*2+1] = fmaxf(c.y, 0.f);
        }
        *(float4*)&g_rec1[(size_t)row*NH + col0 + tx*8]     = *(float4*)&o[0];
        *(float4*)&g_rec1[(size_t)row*NH + col0 + tx*8 + 4] = *(float4*)&o[4];
    }
}

// ---------------- kernel 3: rec2 GEMM 128x128xK256, fused ae_loss + col sums ----------------
__global__ void __launch_bounds__(256) rec2_kernel(const float* __restrict__ f,
                                                   const float* __restrict__ rv2) {
    __shared__ float As[16*128];
    __shared__ float Bs[16*128];
    int tid = threadIdx.x;
    int tx = tid & 15, ty = tid >> 4;
    int col0 = blockIdx.x * 128;
    int row0 = blockIdx.y * 128;

    ull acc2[8][4];
    #pragma unroll
    for (int i = 0; i < 8; i++)
        #pragma unroll
        for (int j = 0; j < 4; j++) acc2[i][j] = 0ull;

    for (int k0 = 0; k0 < NH; k0 += 16) {
        #pragma unroll
        for (int it = 0; it < 2; it++) {
            int v = tid + it*256;
            int r = v >> 2, q = v & 3;
            float4 t4 = *(const float4*)&g_rec1[(size_t)(row0 + r)*NH + k0 + q*4];
            As[(q*4+0)*128 + r] = t4.x;
            As[(q*4+1)*128 + r] = t4.y;
            As[(q*4+2)*128 + r] = t4.z;
            As[(q*4+3)*128 + r] = t4.w;
            int kk = v >> 5, qq = v & 31;
            float4 u4 = *(const float4*)&rv2[(size_t)(k0 + kk)*ND + col0 + qq*4];
            *(float4*)&Bs[kk*128 + qq*4] = u4;
        }
        __syncthreads();
        #pragma unroll
        for (int kk = 0; kk < 16; kk++) {
            float a[8];
            *(float4*)&a[0] = *(const float4*)&As[kk*128 + ty*8];
            *(float4*)&a[4] = *(const float4*)&As[kk*128 + ty*8 + 4];
            ulonglong2 b01 = *(const ulonglong2*)&Bs[kk*128 + tx*8];
            ulonglong2 b23 = *(const ulonglong2*)&Bs[kk*128 + tx*8 + 4];
            ull bb[4] = {b01.x, b01.y, b23.x, b23.y};
            #pragma unroll
            for (int i = 0; i < 8; i++) {
                ull ad = pack_dup(a[i]);
                #pragma unroll
                for (int j = 0; j < 4; j++) ffma2(acc2[i][j], ad, bb[j]);
            }
        }
        __syncthreads();
    }

    // unpack
    float acc[8][8];
    #pragma unroll
    for (int i = 0; i < 8; i++)
        #pragma unroll
        for (int j = 0; j < 4; j++) {
            float2 c = unpack2(acc2[i][j]);
            acc[i][j*2] = c.x; acc[i][j*2+1] = c.y;
        }

    // epilogue: ae_loss + per-col (= per-d) sums over rows (= over s)
    int b = row0 >> 9;
    int sbase = (row0 & 511) + ty*8;
    float invn[8];
    #pragma unroll
    for (int i = 0; i < 8; i++) invn[i] = g_invnorm[row0 + ty*8 + i];
    float aeacc = 0.f;
    float cs[8];
    #pragma unroll
    for (int j = 0; j < 8; j++) cs[j] = 0.f;
    #pragma unroll
    for (int j = 0; j < 8; j++) {
        int col = col0 + tx*8 + j;
        const float* fp = f + ((size_t)(b*ND + col))*NS + sbase;
        #pragma unroll
        for (int i = 0; i < 8; i++) {
            float c = acc[i][j];
            float xn = fp[i] * invn[i];
            float d = xn - c;
            aeacc += d*d;
            cs[j] += c;
        }
    }
    __syncthreads();
    #pragma unroll
    for (int j = 0; j < 8; j++) As[ty*128 + tx*8 + j] = cs[j];
    __syncthreads();
    if (tid < 128) {
        float ssum = 0.f;
        #pragma unroll
        for (int t = 0; t < 16; t++) ssum += As[t*128 + tid];
        atomicAdd(&g_mean[b*ND + col0 + tid], ssum);
    }
    Bs[tid] = aeacc;
    __syncthreads();
    for (int s = 128; s > 0; s >>= 1) { if (tid < s) Bs[tid] += Bs[tid+s]; __syncthreads(); }
    if (tid == 0) atomicAdd(&g_ae, Bs[0]);
}

// ---------------- final: pred head + scalars ----------------
__global__ void final_kernel(const float* __restrict__ Wc, const float* __restrict__ bc,
                             float* __restrict__ out) {
    int tid = threadIdx.x;
    int b = tid >> 1, c = tid & 1;
    float acc = 0.f;
    for (int d = 0; d < ND; d++) acc += g_mean[b*ND + d] * Wc[d*2 + c];
    out[OUT_PRED + b*2 + c] = acc * (1.0f/512.0f) + bc[c];
    if (tid == 0) {
        out[OUT_SCAL0] = 0.0f;
        out[OUT_SIM]   = -g_sim / (float)(NK * (NB/4));
        out[OUT_FAR]   = g_far;
        out[OUT_AE]    = g_ae / (float)((size_t)NROWS * ND);
    }
}

extern "C" void kernel_launch(void* const* d_in, const int* in_sizes, int n_in,
                              void* d_out, int out_size) {
    const float* f   = (const float*)d_in[0];   // f_input [B,D,S]
    const float* tv  = (const float*)d_in[2];   // topic_vector [D,K]
    const float* rv1 = (const float*)d_in[3];   // [K,H]
    const float* rv2 = (const float*)d_in[4];   // [H,D]
    const float* Wc  = (const float*)d_in[5];   // [D,NCLS]
    const float* bc  = (const float*)d_in[6];   // [NCLS]
    float* out = (float*)d_out;

    cudaFuncSetAttribute(rec1_kernel, cudaFuncAttributeMaxDynamicSharedMemorySize, REC1_SMEM);

    prep_kernel<<<1, 256>>>(tv);
    topic_kernel<<<NROWS/128, 256>>>(f, out + OUT_NN);
    topk1_kernel<<<dim3(64, NK), 32>>>();
    rec1_kernel<<<dim3(2, 512), 256, REC1_SMEM>>>(rv1);
    topk2_kernel<<<NK, 256>>>();
    rec2_kernel<<<dim3(ND/128, NROWS/128), 256>>>(f, rv2);
    final_kernel<<<1, 256>>>(Wc, bc, out);
}